// round 1
// baseline (speedup 1.0000x reference)
#include <cuda_runtime.h>

// ConcatenateMeanMax: out[b] = concat(bond_ft[b],
//                                     mean(atom_ft[src[2b]], atom_ft[src[2b+1]]),
//                                     max (atom_ft[src[2b]], atom_ft[src[2b+1]]))
// Exploits edge_dst = repeat(arange(N_BONDS), 2): every segment has exactly 2 edges.
//
// Layout: one warp per bond. lane i handles columns [4i, 4i+4) via float4.
//   - 1x int2 load of the two source indices (8B, aligned)
//   - 2x 512B coalesced gather from atom_ft (random row, contiguous within row)
//   - 1x 512B coalesced read of bond_ft row
//   - 3x 512B coalesced stores into the 1536B output row

#define D 128
#define D4 (D / 4)       // 32 float4 per row == one warp
#define OUT_STRIDE4 (3 * D4)

__global__ __launch_bounds__(256) void concat_mean_max_kernel(
    const float* __restrict__ atom_ft,
    const float* __restrict__ bond_ft,
    const int*   __restrict__ edge_src,
    float* __restrict__ out,
    int n_bonds)
{
    const int gwarp = (blockIdx.x * blockDim.x + threadIdx.x) >> 5;
    const int lane  = threadIdx.x & 31;
    if (gwarp >= n_bonds) return;
    const int b = gwarp;

    // two source atoms for this bond (edges 2b, 2b+1)
    const int2 s = __ldg(((const int2*)edge_src) + b);

    const float4* __restrict__ a0 = (const float4*)(atom_ft + (size_t)s.x * D);
    const float4* __restrict__ a1 = (const float4*)(atom_ft + (size_t)s.y * D);
    const float4* __restrict__ bf = (const float4*)(bond_ft + (size_t)b   * D);

    const float4 v0 = __ldg(a0 + lane);
    const float4 v1 = __ldg(a1 + lane);
    const float4 vb = __ldg(bf + lane);

    float4 mean, mx;
    mean.x = (v0.x + v1.x) * 0.5f;  mx.x = fmaxf(v0.x, v1.x);
    mean.y = (v0.y + v1.y) * 0.5f;  mx.y = fmaxf(v0.y, v1.y);
    mean.z = (v0.z + v1.z) * 0.5f;  mx.z = fmaxf(v0.z, v1.z);
    mean.w = (v0.w + v1.w) * 0.5f;  mx.w = fmaxf(v0.w, v1.w);

    float4* __restrict__ o = (float4*)(out + (size_t)b * (3 * D));
    o[lane]          = vb;    // [0,128)   : bond features
    o[D4 + lane]     = mean;  // [128,256) : segment mean
    o[2 * D4 + lane] = mx;    // [256,384) : segment max
}

extern "C" void kernel_launch(void* const* d_in, const int* in_sizes, int n_in,
                              void* d_out, int out_size)
{
    const float* atom_ft  = (const float*)d_in[0];
    const float* bond_ft  = (const float*)d_in[1];
    const int*   edge_src = (const int*)d_in[2];
    // d_in[3] = edge_dst: structurally repeat(arange(n_bonds), 2); not needed.

    const int n_bonds = in_sizes[1] / D;   // bond_ft element count / 128

    float* out = (float*)d_out;

    // one warp per bond; 8 warps (256 threads) per block
    const int warps_per_block = 256 / 32;
    const int grid = (n_bonds + warps_per_block - 1) / warps_per_block;
    concat_mean_max_kernel<<<grid, 256>>>(atom_ft, bond_ft, edge_src, out, n_bonds);
}

// round 4
// speedup vs baseline: 1.0420x; 1.0420x over previous
#include <cuda_runtime.h>
#include <cstdint>

// ConcatenateMeanMax: out[b] = concat(bond_ft[b],
//                                     mean(atom_ft[src[2b]], atom_ft[src[2b+1]]),
//                                     max (atom_ft[src[2b]], atom_ft[src[2b+1]]))
// edge_dst = repeat(arange(N_BONDS), 2)  =>  segment b is exactly edges {2b, 2b+1}.
//
// R3 = R2 intent with correct PTX: sm_103 ptxas rejects inline
// .L2::evict_last on v4 loads (v8-only); the supported path for 128-bit
// loads is createpolicy + ld.global.nc.L2::cache_hint.
//  - atom gathers : evict_last policy  (pin 102MB atom table in 126MB L2)
//  - bond reads   : evict_first policy (streaming)
//  - out stores   : st.global.cs       (streaming)
//  - 2 independent bonds per warp (deeper MLP)

#define D 128
#define D4 (D / 4)   // 32 float4 per row == one warp

__device__ __forceinline__ uint64_t make_policy_keep() {
    uint64_t p;
    asm("createpolicy.fractional.L2::evict_last.b64 %0, 1.0;" : "=l"(p));
    return p;
}

__device__ __forceinline__ uint64_t make_policy_stream() {
    uint64_t p;
    asm("createpolicy.fractional.L2::evict_first.b64 %0, 1.0;" : "=l"(p));
    return p;
}

__device__ __forceinline__ float4 ldg_hint(const float4* p, uint64_t pol) {
    float4 v;
    asm("ld.global.nc.L2::cache_hint.v4.f32 {%0,%1,%2,%3}, [%4], %5;"
        : "=f"(v.x), "=f"(v.y), "=f"(v.z), "=f"(v.w) : "l"(p), "l"(pol));
    return v;
}

__device__ __forceinline__ void stg_stream(float4* p, float4 v) {
    asm volatile("st.global.cs.v4.f32 [%0], {%1,%2,%3,%4};"
                 :: "l"(p), "f"(v.x), "f"(v.y), "f"(v.z), "f"(v.w));
}

__device__ __forceinline__ void do_bond(
    const float* __restrict__ atom_ft,
    const float* __restrict__ bond_ft,
    float* __restrict__ out,
    int b, int2 s, int lane, uint64_t pol_keep, uint64_t pol_stream)
{
    const float4* a0 = (const float4*)(atom_ft + (size_t)s.x * D);
    const float4* a1 = (const float4*)(atom_ft + (size_t)s.y * D);
    const float4* bf = (const float4*)(bond_ft + (size_t)b   * D);

    const float4 v0 = ldg_hint(a0 + lane, pol_keep);
    const float4 v1 = ldg_hint(a1 + lane, pol_keep);
    const float4 vb = ldg_hint(bf + lane, pol_stream);

    float4 mean, mx;
    mean.x = (v0.x + v1.x) * 0.5f;  mx.x = fmaxf(v0.x, v1.x);
    mean.y = (v0.y + v1.y) * 0.5f;  mx.y = fmaxf(v0.y, v1.y);
    mean.z = (v0.z + v1.z) * 0.5f;  mx.z = fmaxf(v0.z, v1.z);
    mean.w = (v0.w + v1.w) * 0.5f;  mx.w = fmaxf(v0.w, v1.w);

    float4* o = (float4*)(out + (size_t)b * (3 * D));
    stg_stream(o + lane,          vb);
    stg_stream(o + D4 + lane,     mean);
    stg_stream(o + 2 * D4 + lane, mx);
}

__global__ __launch_bounds__(256) void concat_mean_max_kernel(
    const float* __restrict__ atom_ft,
    const float* __restrict__ bond_ft,
    const int*   __restrict__ edge_src,
    float* __restrict__ out,
    int n_bonds)
{
    const int gwarp = (blockIdx.x * blockDim.x + threadIdx.x) >> 5;
    const int lane  = threadIdx.x & 31;

    const uint64_t pol_keep   = make_policy_keep();
    const uint64_t pol_stream = make_policy_stream();

    // two bonds per warp: b0 and b0 + n_half (independent work, deeper MLP)
    const int n_half = (n_bonds + 1) >> 1;
    const int b0 = gwarp;
    if (b0 >= n_half) return;
    const int b1 = b0 + n_half;

    const int2 s0 = __ldg(((const int2*)edge_src) + b0);
    if (b1 < n_bonds) {
        const int2 s1 = __ldg(((const int2*)edge_src) + b1);
        do_bond(atom_ft, bond_ft, out, b0, s0, lane, pol_keep, pol_stream);
        do_bond(atom_ft, bond_ft, out, b1, s1, lane, pol_keep, pol_stream);
    } else {
        do_bond(atom_ft, bond_ft, out, b0, s0, lane, pol_keep, pol_stream);
    }
}

extern "C" void kernel_launch(void* const* d_in, const int* in_sizes, int n_in,
                              void* d_out, int out_size)
{
    const float* atom_ft  = (const float*)d_in[0];
    const float* bond_ft  = (const float*)d_in[1];
    const int*   edge_src = (const int*)d_in[2];
    // d_in[3] = edge_dst: structurally repeat(arange(n_bonds), 2); unused.

    const int n_bonds = in_sizes[1] / D;
    float* out = (float*)d_out;

    const int n_half = (n_bonds + 1) >> 1;       // warps needed (2 bonds/warp)
    const int warps_per_block = 256 / 32;
    const int grid = (n_half + warps_per_block - 1) / warps_per_block;
    concat_mean_max_kernel<<<grid, 256>>>(atom_ft, bond_ft, edge_src, out, n_bonds);
}